// round 15
// baseline (speedup 1.0000x reference)
#include <cuda_runtime.h>
#include <cuda_fp16.h>
#include <cstdint>

// ---------------- problem constants ----------------
#define N_NODES 10000
#define M_PAD   10112            // 79 * 128
#define N_EDGES 100000
#define EE      110000           // edges + self loops
#define G_IN    2000
#define K1_PAD  2048
#define H       20
#define C       128
#define HC      2560             // H * C
#define NEG_SLOPE 0.2f
#define AGG_CH  32               // edge chunk for smem alpha

// ---------------- scratch (device globals; no allocations) ----------------
__device__ __half g_hh[(size_t)N_NODES * HC];    // fp16 GEMM output (for aggregations)
__device__ float  g_asrc[N_NODES * H];
__device__ float  g_adst[N_NODES * H];
__device__ int    g_rowptr[N_NODES + 1];
__device__ int    g_deg[N_NODES];
__device__ int    g_fill[N_NODES];
__device__ int    g_csrc[EE];
__device__ int    g_is64;
__device__ int    g_esrc[N_EDGES];
__device__ int    g_edst[N_EDGES];
// fp16 GEMM operands: A [m][kpad], W^T [n][kpad]
__device__ __half g_ah[(size_t)M_PAD * HC];
__device__ __half g_wt[(size_t)HC * HC];

// ---------------- helpers ----------------
__device__ __forceinline__ uint32_t smem_u32(const void* p) {
    uint32_t a;
    asm("{ .reg .u64 t; cvta.to.shared.u64 t, %1; cvt.u32.u64 %0, t; }" : "=r"(a) : "l"(p));
    return a;
}
#define SWZ(off) ((off) ^ (((off) >> 3) & 0x70))

__device__ __forceinline__ void cp16(uint32_t dst, const void* src) {
    asm volatile("cp.async.cg.shared.global [%0], [%1], 16;" :: "r"(dst), "l"(src) : "memory");
}
__device__ __forceinline__ void cp_commit() {
    asm volatile("cp.async.commit_group;" ::: "memory");
}
template <int X> __device__ __forceinline__ void cp_wait() {
    asm volatile("cp.async.wait_group %0;" :: "n"(X) : "memory");
}
#define LDSM4(r0, r1, r2, r3, addr) \
    asm volatile("ldmatrix.sync.aligned.m8n8.x4.shared.b16 {%0,%1,%2,%3}, [%4];" \
        : "=r"(r0), "=r"(r1), "=r"(r2), "=r"(r3) : "r"(addr))
#define MMA(c, a, b) \
    asm volatile("mma.sync.aligned.m16n8k16.row.col.f32.f16.f16.f32 " \
        "{%0,%1,%2,%3}, {%4,%5,%6,%7}, {%8,%9}, {%0,%1,%2,%3};" \
        : "+f"((c)[0]), "+f"((c)[1]), "+f"((c)[2]), "+f"((c)[3]) \
        : "r"((a)[0]), "r"((a)[1]), "r"((a)[2]), "r"((a)[3]), "r"((b)[0]), "r"((b)[1]))

// ---------------- prep: zero degrees + edge dtype detection ----------------
__global__ void k_prep(const int* __restrict__ ei32) {
    int i = blockIdx.x * blockDim.x + threadIdx.x;
    if (i < N_NODES) g_deg[i] = 0;
    if (blockIdx.x == 0) {
        __shared__ int any;
        if (threadIdx.x == 0) any = 0;
        __syncthreads();
        if (ei32[2 * threadIdx.x + 1] != 0) atomicOr(&any, 1);
        __syncthreads();
        if (threadIdx.x == 0) g_is64 = (any == 0) ? 1 : 0;
    }
}

// ---------------- normalize edges + count degrees (fused) ----------------
__global__ void k_normcount(const int* __restrict__ ei32) {
    int e = blockIdx.x * blockDim.x + threadIdx.x;
    if (e >= EE) return;
    if (e < N_EDGES) {
        int s, d;
        if (g_is64) { s = ei32[2 * e]; d = ei32[2 * N_EDGES + 2 * e]; }
        else        { s = ei32[e];     d = ei32[N_EDGES + e]; }
        g_esrc[e] = s;
        g_edst[e] = d;
        atomicAdd(&g_deg[d], 1);
    } else {
        atomicAdd(&g_deg[e - N_EDGES], 1);
    }
}

__global__ void k_scan() {
    __shared__ int part[1024];
    int t = threadIdx.x;
    const int CH = (N_NODES + 1023) / 1024;
    int base = t * CH, s = 0;
    for (int i = 0; i < CH; i++) { int idx = base + i; if (idx < N_NODES) s += g_deg[idx]; }
    part[t] = s;
    __syncthreads();
    for (int o = 1; o < 1024; o <<= 1) {
        int v = (t >= o) ? part[t - o] : 0;
        __syncthreads(); part[t] += v; __syncthreads();
    }
    int run = (t > 0) ? part[t - 1] : 0;
    for (int i = 0; i < CH; i++) {
        int idx = base + i;
        if (idx < N_NODES) { g_rowptr[idx] = run; g_fill[idx] = run; run += g_deg[idx]; }
    }
    if (t == 1023) g_rowptr[N_NODES] = part[1023];
}
__global__ void k_scatter() {
    int e = blockIdx.x * blockDim.x + threadIdx.x;
    if (e >= EE) return;
    int src, dst;
    if (e < N_EDGES) { src = g_esrc[e]; dst = g_edst[e]; }
    else             { src = e - N_EDGES; dst = src; }
    int pos = atomicAdd(&g_fill[dst], 1);
    g_csrc[pos] = src;
}

// ---------------- layer-1 activation convert: g_ah[m][kpad] = fp16(x[m][k]) ----------------
__global__ void k_acvt(const float* __restrict__ A, int K, int KPAD) {
    int idx = blockIdx.x * blockDim.x + threadIdx.x;
    int rowlen4 = KPAD >> 2;
    if (idx >= N_NODES * rowlen4) return;
    int row = idx / rowlen4;
    int c4  = (idx - row * rowlen4) << 2;
    float v[4];
    #pragma unroll
    for (int j = 0; j < 4; j++) v[j] = (c4 + j < K) ? A[(size_t)row * K + c4 + j] : 0.f;
    uint32_t w0 = (uint32_t)__half_as_ushort(__float2half_rn(v[0]))
                | ((uint32_t)__half_as_ushort(__float2half_rn(v[1])) << 16);
    uint32_t w1 = (uint32_t)__half_as_ushort(__float2half_rn(v[2]))
                | ((uint32_t)__half_as_ushort(__float2half_rn(v[3])) << 16);
    *(uint2*)&g_ah[(size_t)row * KPAD + c4] = make_uint2(w0, w1);
}

// ---------------- W transpose to fp16: g_wt[n][kpad] = fp16(W[k][n]) ----------------
__global__ void k_wsplit(const float* __restrict__ W, int K, int KPAD) {
    __shared__ float tile[32][33];
    int n0 = blockIdx.y * 32, k0 = blockIdx.x * 32;
    int tx = threadIdx.x, ty = threadIdx.y;     // (32, 8)
    #pragma unroll
    for (int s = 0; s < 32; s += 8) {
        int k = k0 + ty + s;
        tile[ty + s][tx] = (k < K) ? W[(size_t)k * HC + n0 + tx] : 0.f;
    }
    __syncthreads();
    #pragma unroll
    for (int s = 0; s < 32; s += 8) {
        int n = n0 + ty + s;
        int k = k0 + tx;
        g_wt[(size_t)n * KPAD + k] = __float2half_rn(tile[tx][ty + s]);
    }
}

// ---------------- fp16 HMMA GEMM + fused attention scores ----------------
// CTA tile 128x128 (= 1 head), 4 warps (128 thr), warp tile 64x64,
// K staged 64, 3-stage cp.async pipeline, 2 CTAs/SM.
#define STG3   32768              // A 16K | B 16K
#define OFF_B  16384
#define GSMEM  (3 * STG3)         // 96 KB

__global__ __launch_bounds__(128, 2)
void k_hgemm(int kpad, const float* __restrict__ wsrc, const float* __restrict__ wdst)
{
    extern __shared__ char smem[];
    uint32_t sb = smem_u32(smem);
    int tid  = threadIdx.x;
    int lane = tid & 31;
    int wid  = tid >> 5;            // 0..3
    int wr   = wid >> 1;            // 0..1  (64-row slabs)
    int wc   = wid & 1;             // 0..1  (64-col slabs)
    int row0 = blockIdx.y * 128;
    int col0 = blockIdx.x * 128;
    int nkb  = kpad >> 6;

    float acc[4][8][4];
    #pragma unroll
    for (int i = 0; i < 4; i++)
        #pragma unroll
        for (int j = 0; j < 8; j++)
            #pragma unroll
            for (int q = 0; q < 4; q++) acc[i][j][q] = 0.f;

    auto issue = [&](int kb) {
        int kt = kb << 6;
        uint32_t st = sb + (kb % 3) * STG3;
        #pragma unroll
        for (int i = 0; i < 8; i++) {                 // A: 128 rows
            int idx = i * 128 + tid;
            int r = idx >> 3, c = idx & 7;
            uint32_t off = SWZ((uint32_t)(r * 128 + c * 16));
            cp16(st + off, g_ah + (size_t)(row0 + r) * kpad + kt + c * 8);
        }
        #pragma unroll
        for (int i = 0; i < 8; i++) {                 // B: 128 rows
            int idx = i * 128 + tid;
            int r = idx >> 3, c = idx & 7;
            uint32_t off = SWZ((uint32_t)(r * 128 + c * 16));
            cp16(st + OFF_B + off, g_wt + (size_t)(col0 + r) * kpad + kt + c * 8);
        }
    };

    issue(0); cp_commit();
    if (nkb > 1) issue(1);
    cp_commit();

    for (int kb = 0; kb < nkb; kb++) {
        cp_wait<1>();
        __syncthreads();
        if (kb + 2 < nkb) issue(kb + 2);
        cp_commit();

        uint32_t tb = sb + (kb % 3) * STG3;
        #pragma unroll
        for (int k16 = 0; k16 < 4; k16++) {
            uint32_t ah[4][4];
            int arow = wr * 64 + (lane & 15);
            uint32_t acol = (uint32_t)(k16 * 32 + (lane >> 4) * 16);
            #pragma unroll
            for (int mt = 0; mt < 4; mt++) {
                uint32_t off = SWZ((uint32_t)((arow + mt * 16) * 128) + acol);
                LDSM4(ah[mt][0], ah[mt][1], ah[mt][2], ah[mt][3], tb + off);
            }
            int mi = lane >> 3;
            int brow = wc * 64 + ((mi >> 1) << 3) + (lane & 7);
            uint32_t bcol = (uint32_t)(k16 * 32 + (mi & 1) * 16);
            #pragma unroll
            for (int half = 0; half < 2; half++) {
                uint32_t bh[4][2];
                #pragma unroll
                for (int q = 0; q < 2; q++) {
                    int nt2 = half * 2 + q;
                    uint32_t off = SWZ((uint32_t)((brow + nt2 * 16) * 128) + bcol);
                    LDSM4(bh[q * 2][0], bh[q * 2][1], bh[q * 2 + 1][0], bh[q * 2 + 1][1],
                          tb + OFF_B + off);
                }
                #pragma unroll
                for (int mt = 0; mt < 4; mt++)
                    #pragma unroll
                    for (int ntl = 0; ntl < 4; ntl++)
                        MMA(acc[mt][half * 4 + ntl], ah[mt], bh[ntl]);
            }
        }
    }

    // ---- epilogue 1: fp16 feature store ----
    #pragma unroll
    for (int mt = 0; mt < 4; mt++) {
        int gr = row0 + wr * 64 + mt * 16 + (lane >> 2);
        #pragma unroll
        for (int nt = 0; nt < 8; nt++) {
            int gc = col0 + wc * 64 + nt * 8 + (lane & 3) * 2;
            if (gr < N_NODES)
                *(__half2*)&g_hh[(size_t)gr * HC + gc] =
                    __floats2half2_rn(acc[mt][nt][0], acc[mt][nt][1]);
            if (gr + 8 < N_NODES)
                *(__half2*)&g_hh[(size_t)(gr + 8) * HC + gc] =
                    __floats2half2_rn(acc[mt][nt][2], acc[mt][nt][3]);
        }
    }

    // ---- epilogue 2: fused attention scores (CTA = head blockIdx.x) ----
    __syncthreads();                      // stage smem no longer needed
    float* s_red = (float*)smem;          // [128 rows][2 contrib][2 src/dst]
    int hdg = blockIdx.x;
    float wS0[8], wS1[8], wD0[8], wD1[8];
    #pragma unroll
    for (int nt = 0; nt < 8; nt++) {
        int cloc = wc * 64 + nt * 8 + (lane & 3) * 2;
        wS0[nt] = __ldg(&wsrc[hdg * C + cloc]);
        wS1[nt] = __ldg(&wsrc[hdg * C + cloc + 1]);
        wD0[nt] = __ldg(&wdst[hdg * C + cloc]);
        wD1[nt] = __ldg(&wdst[hdg * C + cloc + 1]);
    }
    #pragma unroll
    for (int mt = 0; mt < 4; mt++) {
        float sa = 0.f, sbv = 0.f, da = 0.f, db = 0.f;
        #pragma unroll
        for (int nt = 0; nt < 8; nt++) {
            sa  += acc[mt][nt][0] * wS0[nt] + acc[mt][nt][1] * wS1[nt];
            sbv += acc[mt][nt][2] * wS0[nt] + acc[mt][nt][3] * wS1[nt];
            da  += acc[mt][nt][0] * wD0[nt] + acc[mt][nt][1] * wD1[nt];
            db  += acc[mt][nt][2] * wD0[nt] + acc[mt][nt][3] * wD1[nt];
        }
        #pragma unroll
        for (int o = 1; o <= 2; o <<= 1) {
            sa  += __shfl_xor_sync(0xffffffffu, sa,  o);
            sbv += __shfl_xor_sync(0xffffffffu, sbv, o);
            da  += __shfl_xor_sync(0xffffffffu, da,  o);
            db  += __shfl_xor_sync(0xffffffffu, db,  o);
        }
        if ((lane & 3) == 0) {
            int rA = wr * 64 + mt * 16 + (lane >> 2);
            int rB = rA + 8;
            s_red[(rA * 2 + wc) * 2 + 0] = sa;
            s_red[(rA * 2 + wc) * 2 + 1] = da;
            s_red[(rB * 2 + wc) * 2 + 0] = sbv;
            s_red[(rB * 2 + wc) * 2 + 1] = db;
        }
    }
    __syncthreads();
    {
        int gr = row0 + tid;
        if (gr < N_NODES) {
            float vs = s_red[(tid * 2 + 0) * 2 + 0] + s_red[(tid * 2 + 1) * 2 + 0];
            float vd = s_red[(tid * 2 + 0) * 2 + 1] + s_red[(tid * 2 + 1) * 2 + 1];
            g_asrc[gr * H + hdg] = vs;
            g_adst[gr * H + hdg] = vd;
        }
    }
}

// ---------------- layer-1 fused softmax + aggregation ----------------
// 320 threads: alpha phase uses (head = t%20, e-offset = t/20); gather phase
// uses (head = t>>4, 8 cols). out = relu(inv * sum(ex * feat) + b1) -> fp16 g_ah.
__global__ __launch_bounds__(320)
void k_agg1(const float* __restrict__ b1)
{
    __shared__ float s_ex[AGG_CH][20];
    __shared__ float s_ps[320];
    __shared__ float s_inv[20];
    int dst = blockIdx.x;
    int t   = threadIdx.x;
    int hh  = t >> 4;
    int c8  = t * 8;
    int hA  = t % 20;
    int qA  = t / 20;               // 0..15
    int p0 = g_rowptr[dst], p1 = g_rowptr[dst + 1];
    float adA = g_adst[dst * H + hA];
    float psum = 0.f;
    float acc[8];
    #pragma unroll
    for (int j = 0; j < 8; j++) acc[j] = 0.f;

    for (int pc = p0; pc < p1; pc += AGG_CH) {
        int n = min(AGG_CH, p1 - pc);
        // phase A: unnormalized exp into smem
        for (int e = qA; e < n; e += 16) {
            int s = __ldg(&g_csrc[pc + e]);
            float ev = __ldg(&g_asrc[s * H + hA]) + adA;
            ev = (ev > 0.f) ? ev : NEG_SLOPE * ev;
            float ex = __expf(ev);
            s_ex[e][hA] = ex;
            psum += ex;
        }
        __syncthreads();
        // phase B: weighted feature gather
        for (int e = 0; e < n; e++) {
            float al = s_ex[e][hh];
            uint4 v = *(const uint4*)(g_hh + (size_t)__ldg(&g_csrc[pc + e]) * HC + c8);
            float2 f0 = __half22float2(*(__half2*)&v.x), f1 = __half22float2(*(__half2*)&v.y);
            float2 f2 = __half22float2(*(__half2*)&v.z), f3 = __half22float2(*(__half2*)&v.w);
            acc[0] += al * f0.x; acc[1] += al * f0.y;
            acc[2] += al * f1.x; acc[3] += al * f1.y;
            acc[4] += al * f2.x; acc[5] += al * f2.y;
            acc[6] += al * f3.x; acc[7] += al * f3.y;
        }
        __syncthreads();
    }
    // reduce per-head sums (deterministic fixed order)
    s_ps[t] = psum;
    __syncthreads();
    if (t < 20) {
        float s = 0.f;
        #pragma unroll
        for (int q = 0; q < 16; q++) s += s_ps[q * 20 + t];
        s_inv[t] = 1.f / s;
    }
    __syncthreads();
    float inv = s_inv[hh];

    float4 bA = *(const float4*)&b1[c8];
    float4 bB = *(const float4*)&b1[c8 + 4];
    float v0 = fmaxf(acc[0] * inv + bA.x, 0.f), v1 = fmaxf(acc[1] * inv + bA.y, 0.f);
    float v2 = fmaxf(acc[2] * inv + bA.z, 0.f), v3 = fmaxf(acc[3] * inv + bA.w, 0.f);
    float v4 = fmaxf(acc[4] * inv + bB.x, 0.f), v5 = fmaxf(acc[5] * inv + bB.y, 0.f);
    float v6 = fmaxf(acc[6] * inv + bB.z, 0.f), v7 = fmaxf(acc[7] * inv + bB.w, 0.f);
    __half2 o0 = __floats2half2_rn(v0, v1);
    __half2 o1 = __floats2half2_rn(v2, v3);
    __half2 o2 = __floats2half2_rn(v4, v5);
    __half2 o3 = __floats2half2_rn(v6, v7);
    uint4 ov = make_uint4(*(uint32_t*)&o0, *(uint32_t*)&o1, *(uint32_t*)&o2, *(uint32_t*)&o3);
    *(uint4*)(g_ah + (size_t)dst * HC + c8) = ov;
}

// ---------------- layer-2 fused softmax + aggregation (mean over heads) ----------------
__global__ __launch_bounds__(320)
void k_agg2(const float* __restrict__ b2, float* __restrict__ out)
{
    __shared__ float s_ex[AGG_CH][20];
    __shared__ float s_ps[320];
    __shared__ float s_inv[20];
    __shared__ float s_out[C * 20];     // [col][head] partials, 10 KB
    int dst = blockIdx.x;
    int t   = threadIdx.x;
    int hh  = t >> 4;
    int c8  = t * 8;                    // = hh*C + (t&15)*8
    int hA  = t % 20;
    int qA  = t / 20;
    int p0 = g_rowptr[dst], p1 = g_rowptr[dst + 1];
    float adA = g_adst[dst * H + hA];
    float psum = 0.f;
    float acc[8];
    #pragma unroll
    for (int j = 0; j < 8; j++) acc[j] = 0.f;

    for (int pc = p0; pc < p1; pc += AGG_CH) {
        int n = min(AGG_CH, p1 - pc);
        for (int e = qA; e < n; e += 16) {
            int s = __ldg(&g_csrc[pc + e]);
            float ev = __ldg(&g_asrc[s * H + hA]) + adA;
            ev = (ev > 0.f) ? ev : NEG_SLOPE * ev;
            float ex = __expf(ev);
            s_ex[e][hA] = ex;
            psum += ex;
        }
        __syncthreads();
        for (int e = 0; e < n; e++) {
            float al = s_ex[e][hh];
            uint4 v = *(const uint4*)(g_hh + (size_t)__ldg(&g_csrc[pc + e]) * HC + c8);
            float2 f0 = __half22float2(*(__half2*)&v.x), f1 = __half22float2(*(__half2*)&v.y);
            float2 f2 = __half22float2(*(__half2*)&v.z), f3 = __half22float2(*(__half2*)&v.w);
            acc[0] += al * f0.x; acc[1] += al * f0.y;
            acc[2] += al * f1.x; acc[3] += al * f1.y;
            acc[4] += al * f2.x; acc[5] += al * f2.y;
            acc[6] += al * f3.x; acc[7] += al * f3.y;
        }
        __syncthreads();
    }
    s_ps[t] = psum;
    __syncthreads();
    if (t < 20) {
        float s = 0.f;
        #pragma unroll
        for (int q = 0; q < 16; q++) s += s_ps[q * 20 + t];
        s_inv[t] = 1.f / s;
    }
    __syncthreads();
    float inv = s_inv[hh];
    int colb = (t & 15) * 8;            // col base within head
    #pragma unroll
    for (int j = 0; j < 8; j++) s_out[(colb + j) * 20 + hh] = acc[j] * inv;
    __syncthreads();
    if (t < C) {
        float s = 0.f;
        #pragma unroll
        for (int h = 0; h < 20; h++) s += s_out[t * 20 + h];
        float v = s * (1.f / (float)H) + b2[t];
        out[dst * C + t] = (v > 0.f) ? v : 0.f;
    }
}

// ---------------- launch ----------------
extern "C" void kernel_launch(void* const* d_in, const int* in_sizes, int n_in,
                              void* d_out, int out_size)
{
    const float* x   = (const float*)d_in[0];
    const int*   ei  = (const int*)d_in[1];
    const float* W1  = (const float*)d_in[2];
    const float* as1 = (const float*)d_in[3];
    const float* ad1 = (const float*)d_in[4];
    const float* b1  = (const float*)d_in[5];
    const float* W2  = (const float*)d_in[6];
    const float* as2 = (const float*)d_in[7];
    const float* ad2 = (const float*)d_in[8];
    const float* b2  = (const float*)d_in[9];
    float* out = (float*)d_out;

    cudaFuncSetAttribute(k_hgemm, cudaFuncAttributeMaxDynamicSharedMemorySize, GSMEM);

    dim3 gg(HC / 128, M_PAD / 128);                 // (20, 79)
    dim3 wsb(32, 8);

    // ----- layer 1 (k_hgemm at launch #4 so ncu's fixed capture hits it) -----
    int a1blocks = (N_NODES * (K1_PAD / 4) + 255) / 256;
    k_acvt<<<a1blocks, 256>>>(x, G_IN, K1_PAD);                      // 1
    k_wsplit<<<dim3(K1_PAD / 32, HC / 32), wsb>>>(W1, G_IN, K1_PAD); // 2
    k_prep<<<(N_NODES + 255) / 256, 256>>>(ei);                      // 3
    k_hgemm<<<gg, 128, GSMEM>>>(K1_PAD, as1, ad1);                   // 4 (att fused)
    // edge normalization + degree count (fused) + CSR build
    k_normcount<<<(EE + 255) / 256, 256>>>(ei);
    k_scan<<<1, 1024>>>();
    k_scatter<<<(EE + 255) / 256, 256>>>();
    // layer-1 edge phase (softmax fused into agg)
    k_agg1<<<N_NODES, 320>>>(b1);

    // ----- layer 2 -----
    k_wsplit<<<dim3(HC / 32, HC / 32), wsb>>>(W2, HC, HC);
    k_hgemm<<<gg, 128, GSMEM>>>(HC, as2, ad2);
    k_agg2<<<N_NODES, 320>>>(b2, out);
}

// round 16
// speedup vs baseline: 1.0274x; 1.0274x over previous
#include <cuda_runtime.h>
#include <cuda_fp16.h>
#include <cstdint>

// ---------------- problem constants ----------------
#define N_NODES 10000
#define M_PAD   10112            // 79 * 128
#define N_EDGES 100000
#define EE      110000           // edges + self loops
#define G_IN    2000
#define K1_PAD  2048
#define H       20
#define C       128
#define HC      2560             // H * C
#define NEG_SLOPE 0.2f
#define AGG_CH  32               // edge chunk for smem alpha

// ---------------- scratch (device globals; no allocations) ----------------
__device__ __half g_hh[(size_t)N_NODES * HC];    // fp16 GEMM output (for aggregations)
__device__ float  g_asrc[N_NODES * H];
__device__ float  g_adst[N_NODES * H];
__device__ int    g_rowptr[N_NODES + 1];
__device__ int    g_deg[N_NODES];
__device__ int    g_fill[N_NODES];
__device__ int    g_csrc[EE];
__device__ int    g_is64;
__device__ int    g_esrc[N_EDGES];
__device__ int    g_edst[N_EDGES];
// fp16 GEMM operands: A [m][kpad], W^T [n][kpad]
__device__ __half g_ah[(size_t)M_PAD * HC];
__device__ __half g_wt[(size_t)HC * HC];

// ---------------- helpers ----------------
__device__ __forceinline__ uint32_t smem_u32(const void* p) {
    uint32_t a;
    asm("{ .reg .u64 t; cvta.to.shared.u64 t, %1; cvt.u32.u64 %0, t; }" : "=r"(a) : "l"(p));
    return a;
}
#define SWZ(off) ((off) ^ (((off) >> 3) & 0x70))

__device__ __forceinline__ void cp16(uint32_t dst, const void* src) {
    asm volatile("cp.async.cg.shared.global [%0], [%1], 16;" :: "r"(dst), "l"(src) : "memory");
}
__device__ __forceinline__ void cp_commit() {
    asm volatile("cp.async.commit_group;" ::: "memory");
}
template <int X> __device__ __forceinline__ void cp_wait() {
    asm volatile("cp.async.wait_group %0;" :: "n"(X) : "memory");
}
#define LDSM4(r0, r1, r2, r3, addr) \
    asm volatile("ldmatrix.sync.aligned.m8n8.x4.shared.b16 {%0,%1,%2,%3}, [%4];" \
        : "=r"(r0), "=r"(r1), "=r"(r2), "=r"(r3) : "r"(addr))
#define MMA(c, a, b) \
    asm volatile("mma.sync.aligned.m16n8k16.row.col.f32.f16.f16.f32 " \
        "{%0,%1,%2,%3}, {%4,%5,%6,%7}, {%8,%9}, {%0,%1,%2,%3};" \
        : "+f"((c)[0]), "+f"((c)[1]), "+f"((c)[2]), "+f"((c)[3]) \
        : "r"((a)[0]), "r"((a)[1]), "r"((a)[2]), "r"((a)[3]), "r"((b)[0]), "r"((b)[1]))

// ---------------- prep: zero degrees + edge dtype detection ----------------
__global__ void k_prep(const int* __restrict__ ei32) {
    int i = blockIdx.x * blockDim.x + threadIdx.x;
    if (i < N_NODES) g_deg[i] = 0;
    if (blockIdx.x == 0) {
        __shared__ int any;
        if (threadIdx.x == 0) any = 0;
        __syncthreads();
        if (ei32[2 * threadIdx.x + 1] != 0) atomicOr(&any, 1);
        __syncthreads();
        if (threadIdx.x == 0) g_is64 = (any == 0) ? 1 : 0;
    }
}

// ---------------- normalize edges + count degrees (fused) ----------------
__global__ void k_normcount(const int* __restrict__ ei32) {
    int e = blockIdx.x * blockDim.x + threadIdx.x;
    if (e >= EE) return;
    if (e < N_EDGES) {
        int s, d;
        if (g_is64) { s = ei32[2 * e]; d = ei32[2 * N_EDGES + 2 * e]; }
        else        { s = ei32[e];     d = ei32[N_EDGES + e]; }
        g_esrc[e] = s;
        g_edst[e] = d;
        atomicAdd(&g_deg[d], 1);
    } else {
        atomicAdd(&g_deg[e - N_EDGES], 1);
    }
}

__global__ void k_scan() {
    __shared__ int part[1024];
    int t = threadIdx.x;
    const int CH = (N_NODES + 1023) / 1024;
    int base = t * CH, s = 0;
    for (int i = 0; i < CH; i++) { int idx = base + i; if (idx < N_NODES) s += g_deg[idx]; }
    part[t] = s;
    __syncthreads();
    for (int o = 1; o < 1024; o <<= 1) {
        int v = (t >= o) ? part[t - o] : 0;
        __syncthreads(); part[t] += v; __syncthreads();
    }
    int run = (t > 0) ? part[t - 1] : 0;
    for (int i = 0; i < CH; i++) {
        int idx = base + i;
        if (idx < N_NODES) { g_rowptr[idx] = run; g_fill[idx] = run; run += g_deg[idx]; }
    }
    if (t == 1023) g_rowptr[N_NODES] = part[1023];
}
__global__ void k_scatter() {
    int e = blockIdx.x * blockDim.x + threadIdx.x;
    if (e >= EE) return;
    int src, dst;
    if (e < N_EDGES) { src = g_esrc[e]; dst = g_edst[e]; }
    else             { src = e - N_EDGES; dst = src; }
    int pos = atomicAdd(&g_fill[dst], 1);
    g_csrc[pos] = src;
}

// ---------------- layer-1 activation convert: g_ah[m][kpad] = fp16(x[m][k]) ----------------
__global__ void k_acvt(const float* __restrict__ A, int K, int KPAD) {
    int idx = blockIdx.x * blockDim.x + threadIdx.x;
    int rowlen4 = KPAD >> 2;
    if (idx >= N_NODES * rowlen4) return;
    int row = idx / rowlen4;
    int c4  = (idx - row * rowlen4) << 2;
    float v[4];
    #pragma unroll
    for (int j = 0; j < 4; j++) v[j] = (c4 + j < K) ? A[(size_t)row * K + c4 + j] : 0.f;
    uint32_t w0 = (uint32_t)__half_as_ushort(__float2half_rn(v[0]))
                | ((uint32_t)__half_as_ushort(__float2half_rn(v[1])) << 16);
    uint32_t w1 = (uint32_t)__half_as_ushort(__float2half_rn(v[2]))
                | ((uint32_t)__half_as_ushort(__float2half_rn(v[3])) << 16);
    *(uint2*)&g_ah[(size_t)row * KPAD + c4] = make_uint2(w0, w1);
}

// ---------------- W transpose to fp16: g_wt[n][kpad] = fp16(W[k][n]) ----------------
__global__ void k_wsplit(const float* __restrict__ W, int K, int KPAD) {
    __shared__ float tile[32][33];
    int n0 = blockIdx.y * 32, k0 = blockIdx.x * 32;
    int tx = threadIdx.x, ty = threadIdx.y;     // (32, 8)
    #pragma unroll
    for (int s = 0; s < 32; s += 8) {
        int k = k0 + ty + s;
        tile[ty + s][tx] = (k < K) ? W[(size_t)k * HC + n0 + tx] : 0.f;
    }
    __syncthreads();
    #pragma unroll
    for (int s = 0; s < 32; s += 8) {
        int n = n0 + ty + s;
        int k = k0 + tx;
        g_wt[(size_t)n * KPAD + k] = __float2half_rn(tile[tx][ty + s]);
    }
}

// ---------------- fp16 HMMA GEMM + fused attention scores ----------------
// CTA tile 128x128 (= 1 head), 4 warps (128 thr), warp tile 64x64,
// K staged 64, 3-stage cp.async pipeline, 2 CTAs/SM.
#define STG3   32768              // A 16K | B 16K
#define OFF_B  16384
#define GSMEM  (3 * STG3)         // 96 KB

__global__ __launch_bounds__(128, 2)
void k_hgemm(int kpad, const float* __restrict__ wsrc, const float* __restrict__ wdst)
{
    extern __shared__ char smem[];
    uint32_t sb = smem_u32(smem);
    int tid  = threadIdx.x;
    int lane = tid & 31;
    int wid  = tid >> 5;            // 0..3
    int wr   = wid >> 1;            // 0..1  (64-row slabs)
    int wc   = wid & 1;             // 0..1  (64-col slabs)
    int row0 = blockIdx.y * 128;
    int col0 = blockIdx.x * 128;
    int nkb  = kpad >> 6;

    float acc[4][8][4];
    #pragma unroll
    for (int i = 0; i < 4; i++)
        #pragma unroll
        for (int j = 0; j < 8; j++)
            #pragma unroll
            for (int q = 0; q < 4; q++) acc[i][j][q] = 0.f;

    auto issue = [&](int kb) {
        int kt = kb << 6;
        uint32_t st = sb + (kb % 3) * STG3;
        #pragma unroll
        for (int i = 0; i < 8; i++) {                 // A: 128 rows
            int idx = i * 128 + tid;
            int r = idx >> 3, c = idx & 7;
            uint32_t off = SWZ((uint32_t)(r * 128 + c * 16));
            cp16(st + off, g_ah + (size_t)(row0 + r) * kpad + kt + c * 8);
        }
        #pragma unroll
        for (int i = 0; i < 8; i++) {                 // B: 128 rows
            int idx = i * 128 + tid;
            int r = idx >> 3, c = idx & 7;
            uint32_t off = SWZ((uint32_t)(r * 128 + c * 16));
            cp16(st + OFF_B + off, g_wt + (size_t)(col0 + r) * kpad + kt + c * 8);
        }
    };

    issue(0); cp_commit();
    if (nkb > 1) issue(1);
    cp_commit();

    for (int kb = 0; kb < nkb; kb++) {
        cp_wait<1>();
        __syncthreads();
        if (kb + 2 < nkb) issue(kb + 2);
        cp_commit();

        uint32_t tb = sb + (kb % 3) * STG3;
        #pragma unroll
        for (int k16 = 0; k16 < 4; k16++) {
            uint32_t ah[4][4];
            int arow = wr * 64 + (lane & 15);
            uint32_t acol = (uint32_t)(k16 * 32 + (lane >> 4) * 16);
            #pragma unroll
            for (int mt = 0; mt < 4; mt++) {
                uint32_t off = SWZ((uint32_t)((arow + mt * 16) * 128) + acol);
                LDSM4(ah[mt][0], ah[mt][1], ah[mt][2], ah[mt][3], tb + off);
            }
            int mi = lane >> 3;
            int brow = wc * 64 + ((mi >> 1) << 3) + (lane & 7);
            uint32_t bcol = (uint32_t)(k16 * 32 + (mi & 1) * 16);
            #pragma unroll
            for (int half = 0; half < 2; half++) {
                uint32_t bh[4][2];
                #pragma unroll
                for (int q = 0; q < 2; q++) {
                    int nt2 = half * 2 + q;
                    uint32_t off = SWZ((uint32_t)((brow + nt2 * 16) * 128) + bcol);
                    LDSM4(bh[q * 2][0], bh[q * 2][1], bh[q * 2 + 1][0], bh[q * 2 + 1][1],
                          tb + OFF_B + off);
                }
                #pragma unroll
                for (int mt = 0; mt < 4; mt++)
                    #pragma unroll
                    for (int ntl = 0; ntl < 4; ntl++)
                        MMA(acc[mt][half * 4 + ntl], ah[mt], bh[ntl]);
            }
        }
    }

    // ---- epilogue 1: fp16 feature store ----
    #pragma unroll
    for (int mt = 0; mt < 4; mt++) {
        int gr = row0 + wr * 64 + mt * 16 + (lane >> 2);
        #pragma unroll
        for (int nt = 0; nt < 8; nt++) {
            int gc = col0 + wc * 64 + nt * 8 + (lane & 3) * 2;
            if (gr < N_NODES)
                *(__half2*)&g_hh[(size_t)gr * HC + gc] =
                    __floats2half2_rn(acc[mt][nt][0], acc[mt][nt][1]);
            if (gr + 8 < N_NODES)
                *(__half2*)&g_hh[(size_t)(gr + 8) * HC + gc] =
                    __floats2half2_rn(acc[mt][nt][2], acc[mt][nt][3]);
        }
    }

    // ---- epilogue 2: fused attention scores (CTA = head blockIdx.x) ----
    __syncthreads();                      // stage smem no longer needed
    float* s_red = (float*)smem;          // [128 rows][2 contrib][2 src/dst]
    int hdg = blockIdx.x;
    float wS0[8], wS1[8], wD0[8], wD1[8];
    #pragma unroll
    for (int nt = 0; nt < 8; nt++) {
        int cloc = wc * 64 + nt * 8 + (lane & 3) * 2;
        wS0[nt] = __ldg(&wsrc[hdg * C + cloc]);
        wS1[nt] = __ldg(&wsrc[hdg * C + cloc + 1]);
        wD0[nt] = __ldg(&wdst[hdg * C + cloc]);
        wD1[nt] = __ldg(&wdst[hdg * C + cloc + 1]);
    }
    #pragma unroll
    for (int mt = 0; mt < 4; mt++) {
        float sa = 0.f, sbv = 0.f, da = 0.f, db = 0.f;
        #pragma unroll
        for (int nt = 0; nt < 8; nt++) {
            sa  += acc[mt][nt][0] * wS0[nt] + acc[mt][nt][1] * wS1[nt];
            sbv += acc[mt][nt][2] * wS0[nt] + acc[mt][nt][3] * wS1[nt];
            da  += acc[mt][nt][0] * wD0[nt] + acc[mt][nt][1] * wD1[nt];
            db  += acc[mt][nt][2] * wD0[nt] + acc[mt][nt][3] * wD1[nt];
        }
        #pragma unroll
        for (int o = 1; o <= 2; o <<= 1) {
            sa  += __shfl_xor_sync(0xffffffffu, sa,  o);
            sbv += __shfl_xor_sync(0xffffffffu, sbv, o);
            da  += __shfl_xor_sync(0xffffffffu, da,  o);
            db  += __shfl_xor_sync(0xffffffffu, db,  o);
        }
        if ((lane & 3) == 0) {
            int rA = wr * 64 + mt * 16 + (lane >> 2);
            int rB = rA + 8;
            s_red[(rA * 2 + wc) * 2 + 0] = sa;
            s_red[(rA * 2 + wc) * 2 + 1] = da;
            s_red[(rB * 2 + wc) * 2 + 0] = sbv;
            s_red[(rB * 2 + wc) * 2 + 1] = db;
        }
    }
    __syncthreads();
    {
        int gr = row0 + tid;
        if (gr < N_NODES) {
            float vs = s_red[(tid * 2 + 0) * 2 + 0] + s_red[(tid * 2 + 1) * 2 + 0];
            float vd = s_red[(tid * 2 + 0) * 2 + 1] + s_red[(tid * 2 + 1) * 2 + 1];
            g_asrc[gr * H + hdg] = vs;
            g_adst[gr * H + hdg] = vd;
        }
    }
}

// ---------------- layer-1 fused softmax + aggregation ----------------
// 320 threads. Phase A: exp into smem (head = t%20, e-off = t/20) + csrc chunk.
// Phase B: 4-edge-unrolled weighted gather (head = t>>4, 8 cols).
__global__ __launch_bounds__(320)
void k_agg1(const float* __restrict__ b1)
{
    __shared__ float s_ex[AGG_CH][20];
    __shared__ int   s_src[AGG_CH];
    __shared__ float s_ps[320];
    __shared__ float s_inv[20];
    int dst = blockIdx.x;
    int t   = threadIdx.x;
    int hh  = t >> 4;
    int c8  = t * 8;
    int hA  = t % 20;
    int qA  = t / 20;               // 0..15
    int p0 = g_rowptr[dst], p1 = g_rowptr[dst + 1];
    float adA = g_adst[dst * H + hA];
    float psum = 0.f;
    float acc[8];
    #pragma unroll
    for (int j = 0; j < 8; j++) acc[j] = 0.f;

    for (int pc = p0; pc < p1; pc += AGG_CH) {
        int n = min(AGG_CH, p1 - pc);
        if (t < n) s_src[t] = __ldg(&g_csrc[pc + t]);
        for (int e = qA; e < n; e += 16) {
            int s = __ldg(&g_csrc[pc + e]);
            float ev = __ldg(&g_asrc[s * H + hA]) + adA;
            ev = (ev > 0.f) ? ev : NEG_SLOPE * ev;
            float ex = __expf(ev);
            s_ex[e][hA] = ex;
            psum += ex;
        }
        __syncthreads();
        // 4-edge unrolled gather
        int e = 0;
        for (; e + 4 <= n; e += 4) {
            float al[4];
            uint4 v[4];
            #pragma unroll
            for (int q = 0; q < 4; q++) {
                al[q] = s_ex[e + q][hh];
                v[q]  = *(const uint4*)(g_hh + (size_t)s_src[e + q] * HC + c8);
            }
            #pragma unroll
            for (int q = 0; q < 4; q++) {
                float2 f0 = __half22float2(*(__half2*)&v[q].x);
                float2 f1 = __half22float2(*(__half2*)&v[q].y);
                float2 f2 = __half22float2(*(__half2*)&v[q].z);
                float2 f3 = __half22float2(*(__half2*)&v[q].w);
                acc[0] += al[q] * f0.x; acc[1] += al[q] * f0.y;
                acc[2] += al[q] * f1.x; acc[3] += al[q] * f1.y;
                acc[4] += al[q] * f2.x; acc[5] += al[q] * f2.y;
                acc[6] += al[q] * f3.x; acc[7] += al[q] * f3.y;
            }
        }
        for (; e < n; e++) {
            float al = s_ex[e][hh];
            uint4 v = *(const uint4*)(g_hh + (size_t)s_src[e] * HC + c8);
            float2 f0 = __half22float2(*(__half2*)&v.x), f1 = __half22float2(*(__half2*)&v.y);
            float2 f2 = __half22float2(*(__half2*)&v.z), f3 = __half22float2(*(__half2*)&v.w);
            acc[0] += al * f0.x; acc[1] += al * f0.y;
            acc[2] += al * f1.x; acc[3] += al * f1.y;
            acc[4] += al * f2.x; acc[5] += al * f2.y;
            acc[6] += al * f3.x; acc[7] += al * f3.y;
        }
        __syncthreads();
    }
    s_ps[t] = psum;
    __syncthreads();
    if (t < 20) {
        float s = 0.f;
        #pragma unroll
        for (int q = 0; q < 16; q++) s += s_ps[q * 20 + t];
        s_inv[t] = 1.f / s;
    }
    __syncthreads();
    float inv = s_inv[hh];

    float4 bA = *(const float4*)&b1[c8];
    float4 bB = *(const float4*)&b1[c8 + 4];
    float v0 = fmaxf(acc[0] * inv + bA.x, 0.f), v1 = fmaxf(acc[1] * inv + bA.y, 0.f);
    float v2 = fmaxf(acc[2] * inv + bA.z, 0.f), v3 = fmaxf(acc[3] * inv + bA.w, 0.f);
    float v4 = fmaxf(acc[4] * inv + bB.x, 0.f), v5 = fmaxf(acc[5] * inv + bB.y, 0.f);
    float v6 = fmaxf(acc[6] * inv + bB.z, 0.f), v7 = fmaxf(acc[7] * inv + bB.w, 0.f);
    __half2 o0 = __floats2half2_rn(v0, v1);
    __half2 o1 = __floats2half2_rn(v2, v3);
    __half2 o2 = __floats2half2_rn(v4, v5);
    __half2 o3 = __floats2half2_rn(v6, v7);
    uint4 ov = make_uint4(*(uint32_t*)&o0, *(uint32_t*)&o1, *(uint32_t*)&o2, *(uint32_t*)&o3);
    *(uint4*)(g_ah + (size_t)dst * HC + c8) = ov;
}

// ---------------- layer-2 fused softmax + aggregation (mean over heads) ----------------
__global__ __launch_bounds__(320)
void k_agg2(const float* __restrict__ b2, float* __restrict__ out)
{
    __shared__ float s_ex[AGG_CH][20];
    __shared__ int   s_src[AGG_CH];
    __shared__ float s_ps[320];
    __shared__ float s_inv[20];
    __shared__ float s_out[C * 20];     // [col][head] partials, 10 KB
    int dst = blockIdx.x;
    int t   = threadIdx.x;
    int hh  = t >> 4;
    int c8  = t * 8;                    // = hh*C + (t&15)*8
    int hA  = t % 20;
    int qA  = t / 20;
    int p0 = g_rowptr[dst], p1 = g_rowptr[dst + 1];
    float adA = g_adst[dst * H + hA];
    float psum = 0.f;
    float acc[8];
    #pragma unroll
    for (int j = 0; j < 8; j++) acc[j] = 0.f;

    for (int pc = p0; pc < p1; pc += AGG_CH) {
        int n = min(AGG_CH, p1 - pc);
        if (t < n) s_src[t] = __ldg(&g_csrc[pc + t]);
        for (int e = qA; e < n; e += 16) {
            int s = __ldg(&g_csrc[pc + e]);
            float ev = __ldg(&g_asrc[s * H + hA]) + adA;
            ev = (ev > 0.f) ? ev : NEG_SLOPE * ev;
            float ex = __expf(ev);
            s_ex[e][hA] = ex;
            psum += ex;
        }
        __syncthreads();
        int e = 0;
        for (; e + 4 <= n; e += 4) {
            float al[4];
            uint4 v[4];
            #pragma unroll
            for (int q = 0; q < 4; q++) {
                al[q] = s_ex[e + q][hh];
                v[q]  = *(const uint4*)(g_hh + (size_t)s_src[e + q] * HC + c8);
            }
            #pragma unroll
            for (int q = 0; q < 4; q++) {
                float2 f0 = __half22float2(*(__half2*)&v[q].x);
                float2 f1 = __half22float2(*(__half2*)&v[q].y);
                float2 f2 = __half22float2(*(__half2*)&v[q].z);
                float2 f3 = __half22float2(*(__half2*)&v[q].w);
                acc[0] += al[q] * f0.x; acc[1] += al[q] * f0.y;
                acc[2] += al[q] * f1.x; acc[3] += al[q] * f1.y;
                acc[4] += al[q] * f2.x; acc[5] += al[q] * f2.y;
                acc[6] += al[q] * f3.x; acc[7] += al[q] * f3.y;
            }
        }
        for (; e < n; e++) {
            float al = s_ex[e][hh];
            uint4 v = *(const uint4*)(g_hh + (size_t)s_src[e] * HC + c8);
            float2 f0 = __half22float2(*(__half2*)&v.x), f1 = __half22float2(*(__half2*)&v.y);
            float2 f2 = __half22float2(*(__half2*)&v.z), f3 = __half22float2(*(__half2*)&v.w);
            acc[0] += al * f0.x; acc[1] += al * f0.y;
            acc[2] += al * f1.x; acc[3] += al * f1.y;
            acc[4] += al * f2.x; acc[5] += al * f2.y;
            acc[6] += al * f3.x; acc[7] += al * f3.y;
        }
        __syncthreads();
    }
    s_ps[t] = psum;
    __syncthreads();
    if (t < 20) {
        float s = 0.f;
        #pragma unroll
        for (int q = 0; q < 16; q++) s += s_ps[q * 20 + t];
        s_inv[t] = 1.f / s;
    }
    __syncthreads();
    float inv = s_inv[hh];
    int colb = (t & 15) * 8;            // col base within head
    #pragma unroll
    for (int j = 0; j < 8; j++) s_out[(colb + j) * 20 + hh] = acc[j] * inv;
    __syncthreads();
    if (t < C) {
        float s = 0.f;
        #pragma unroll
        for (int h = 0; h < 20; h++) s += s_out[t * 20 + h];
        float v = s * (1.f / (float)H) + b2[t];
        out[dst * C + t] = (v > 0.f) ? v : 0.f;
    }
}

// ---------------- launch ----------------
extern "C" void kernel_launch(void* const* d_in, const int* in_sizes, int n_in,
                              void* d_out, int out_size)
{
    const float* x   = (const float*)d_in[0];
    const int*   ei  = (const int*)d_in[1];
    const float* W1  = (const float*)d_in[2];
    const float* as1 = (const float*)d_in[3];
    const float* ad1 = (const float*)d_in[4];
    const float* b1  = (const float*)d_in[5];
    const float* W2  = (const float*)d_in[6];
    const float* as2 = (const float*)d_in[7];
    const float* ad2 = (const float*)d_in[8];
    const float* b2  = (const float*)d_in[9];
    float* out = (float*)d_out;

    cudaFuncSetAttribute(k_hgemm, cudaFuncAttributeMaxDynamicSharedMemorySize, GSMEM);

    dim3 gg(HC / 128, M_PAD / 128);                 // (20, 79)
    dim3 wsb(32, 8);

    // ----- layer 1 (k_hgemm at launch #4 so ncu's fixed capture hits it) -----
    int a1blocks = (N_NODES * (K1_PAD / 4) + 255) / 256;
    k_acvt<<<a1blocks, 256>>>(x, G_IN, K1_PAD);                      // 1
    k_wsplit<<<dim3(K1_PAD / 32, HC / 32), wsb>>>(W1, G_IN, K1_PAD); // 2
    k_prep<<<(N_NODES + 255) / 256, 256>>>(ei);                      // 3
    k_hgemm<<<gg, 128, GSMEM>>>(K1_PAD, as1, ad1);                   // 4 (att fused)
    // edge normalization + degree count (fused) + CSR build
    k_normcount<<<(EE + 255) / 256, 256>>>(ei);
    k_scan<<<1, 1024>>>();
    k_scatter<<<(EE + 255) / 256, 256>>>();
    // layer-1 edge phase (softmax fused into agg)
    k_agg1<<<N_NODES, 320>>>(b1);

    // ----- layer 2 -----
    k_wsplit<<<dim3(HC / 32, HC / 32), wsb>>>(W2, HC, HC);
    k_hgemm<<<gg, 128, GSMEM>>>(HC, as2, ad2);
    k_agg2<<<N_NODES, 320>>>(b2, out);
}